// round 5
// baseline (speedup 1.0000x reference)
#include <cuda_runtime.h>
#include <cuda_bf16.h>
#include <math.h>
#include <stdint.h>

#define NTOK 16384
#define CDIM 8192
#define HDIM 2048
#define IDIM 8192

// ---------------------------------------------------------------------------
// Scratch (__device__ globals; allocation-free rule)
// ---------------------------------------------------------------------------
__device__ __align__(256) __nv_bfloat16 g_Wgh[(size_t)IDIM * HDIM];
__device__ __align__(256) __nv_bfloat16 g_Wgl[(size_t)IDIM * HDIM];
__device__ __align__(256) __nv_bfloat16 g_Wuh[(size_t)IDIM * HDIM];
__device__ __align__(256) __nv_bfloat16 g_Wul[(size_t)IDIM * HDIM];
__device__ __align__(256) __nv_bfloat16 g_Wdh[(size_t)HDIM * IDIM];
__device__ __align__(256) __nv_bfloat16 g_Wdl[(size_t)HDIM * IDIM];
__device__ __align__(256) float g_h[(size_t)CDIM * IDIM];      // silu(g)*u
__device__ __align__(256) float g_down[(size_t)CDIM * HDIM];

// ---------------------------------------------------------------------------
// helpers (plain sm_80-era PTX only)
// ---------------------------------------------------------------------------
__device__ __forceinline__ uint32_t smem_u32(const void* p) {
    return (uint32_t)__cvta_generic_to_shared(p);
}
__device__ __forceinline__ void ldsm4(uint32_t a, uint32_t& r0, uint32_t& r1,
                                      uint32_t& r2, uint32_t& r3) {
    asm volatile("ldmatrix.sync.aligned.m8n8.x4.shared.b16 {%0,%1,%2,%3}, [%4];"
                 : "=r"(r0), "=r"(r1), "=r"(r2), "=r"(r3) : "r"(a));
}
__device__ __forceinline__ void hmma(float* c, const uint32_t* a,
                                     uint32_t b0, uint32_t b1) {
    asm volatile(
        "mma.sync.aligned.m16n8k16.row.col.f32.bf16.bf16.f32 "
        "{%0,%1,%2,%3},{%4,%5,%6,%7},{%8,%9},{%0,%1,%2,%3};"
        : "+f"(c[0]), "+f"(c[1]), "+f"(c[2]), "+f"(c[3])
        : "r"(a[0]), "r"(a[1]), "r"(a[2]), "r"(a[3]), "r"(b0), "r"(b1));
}
#define CP16(dst, src) \
    asm volatile("cp.async.cg.shared.global [%0], [%1], 16;" \
                 :: "r"(dst), "l"(src))
#define CP_COMMIT() asm volatile("cp.async.commit_group;")
#define CP_WAIT0()  asm volatile("cp.async.wait_group 0;")

// fp32 -> (hi, lo) bf16 split of 4 consecutive K elements; 8B packed stores
__device__ __forceinline__ void split_store(char* hi, char* lo, float4 v) {
    __nv_bfloat162 h0 = __floats2bfloat162_rn(v.x, v.y);
    __nv_bfloat162 h1 = __floats2bfloat162_rn(v.z, v.w);
    float2 f0 = __bfloat1622float2(h0);
    float2 f1 = __bfloat1622float2(h1);
    __nv_bfloat162 l0 = __floats2bfloat162_rn(v.x - f0.x, v.y - f0.y);
    __nv_bfloat162 l1 = __floats2bfloat162_rn(v.z - f1.x, v.w - f1.y);
    uint32_t h0u = *reinterpret_cast<uint32_t*>(&h0);
    uint32_t h1u = *reinterpret_cast<uint32_t*>(&h1);
    uint32_t l0u = *reinterpret_cast<uint32_t*>(&l0);
    uint32_t l1u = *reinterpret_cast<uint32_t*>(&l1);
    *reinterpret_cast<uint2*>(hi) = make_uint2(h0u, h1u);
    *reinterpret_cast<uint2*>(lo) = make_uint2(l0u, l1u);
}
__device__ __forceinline__ void split4(float4 v, uint2& hi, uint2& lo) {
    __nv_bfloat162 h0 = __floats2bfloat162_rn(v.x, v.y);
    __nv_bfloat162 h1 = __floats2bfloat162_rn(v.z, v.w);
    float2 f0 = __bfloat1622float2(h0);
    float2 f1 = __bfloat1622float2(h1);
    __nv_bfloat162 l0 = __floats2bfloat162_rn(v.x - f0.x, v.y - f0.y);
    __nv_bfloat162 l1 = __floats2bfloat162_rn(v.z - f1.x, v.w - f1.y);
    hi = make_uint2(*reinterpret_cast<uint32_t*>(&h0), *reinterpret_cast<uint32_t*>(&h1));
    lo = make_uint2(*reinterpret_cast<uint32_t*>(&l0), *reinterpret_cast<uint32_t*>(&l1));
}
__device__ __forceinline__ float silu(float g) { return g / (1.f + expf(-g)); }

// smem rows: 32 bf16 padded to 40 (80B = 5x16B) — conflict-free ldmatrix (R3)
#define ROWB 80
// k1 stage sections: A_hi | A_lo | Bg_hi | Bg_lo | Bu_hi | Bu_lo
#define K1_ALO   10240
#define K1_BGHI  20480
#define K1_BGLO  30720
#define K1_BUHI  40960
#define K1_BULO  51200
#define STAGE1   61440
#define SMEM1    (2 * STAGE1)
// k2 stage sections: A_hi | A_lo | B_hi | B_lo
#define K2_ALO   10240
#define K2_BHI   20480
#define K2_BLO   30720
#define STAGE2   40960
#define SMEM2    (2 * STAGE2)

#define NC1 (HDIM / 32)   // 64 chunks
#define NC2 (IDIM / 32)   // 256 chunks

// ---------------------------------------------------------------------------
// pre-pass: fp32 weight -> bf16 hi/lo planes
// ---------------------------------------------------------------------------
__global__ __launch_bounds__(256)
void conv_w(const float4* __restrict__ W, __nv_bfloat16* __restrict__ hi,
            __nv_bfloat16* __restrict__ lo, int n4)
{
    for (int i = blockIdx.x * 256 + threadIdx.x; i < n4; i += gridDim.x * 256) {
        uint2 h, l;
        split4(W[i], h, l);
        *reinterpret_cast<uint2*>(hi + 4 * (size_t)i) = h;
        *reinterpret_cast<uint2*>(lo + 4 * (size_t)i) = l;
    }
}

// ---------------------------------------------------------------------------
// Kernel 1: gather + dual GEMM (gate,up) bf16-split-3 HMMA + SiLU epilogue
// R3 structure: warps 0-3 gate / 4-7 up; A register-staged+split, B cp.async.
// ---------------------------------------------------------------------------
__global__ __launch_bounds__(256)
void k1_gateup(const float* __restrict__ x, const int* __restrict__ fg)
{
    extern __shared__ __align__(128) char sm[];
    const uint32_t smb = smem_u32(sm);
    const int tid  = threadIdx.x;
    const int wid  = tid >> 5;
    const int lane = tid & 31;
    const int m0 = blockIdx.x * 128;   // m fastest -> B tiles L2-resident
    const int n0 = blockIdx.y * 128;

    // A staging geometry (R3): 8 threads/row, one float4 each, 4 rows/thread
    const int rbase = tid >> 3;
    const int c4    = (tid & 7) * 4;
    const float* pA[4];
    int sts[4];
#pragma unroll
    for (int j = 0; j < 4; j++) {
        int row = rbase + 32 * j;
        pA[j] = x + (size_t)__ldg(fg + m0 + row) * HDIM + c4;
        sts[j] = row * ROWB + (tid & 7) * 8;
    }

    // B cp.async geometry: 2 threads/row, 2 chunks of 16B per plane
    const int brow  = tid >> 1;
    const int bch   = (tid & 1) * 2;
    const size_t bRow = (size_t)(n0 + brow) * HDIM;
    const uint32_t bd0 = (uint32_t)(brow * ROWB + bch * 16);
    const uint32_t bd1 = bd0 + 16;

#define K1_ISSUE_B(SB, K0) do {                                                \
    const int ke0 = (K0) + bch * 8;                                            \
    CP16((SB) + K1_BGHI + bd0, g_Wgh + bRow + ke0);                            \
    CP16((SB) + K1_BGHI + bd1, g_Wgh + bRow + ke0 + 8);                        \
    CP16((SB) + K1_BGLO + bd0, g_Wgl + bRow + ke0);                            \
    CP16((SB) + K1_BGLO + bd1, g_Wgl + bRow + ke0 + 8);                        \
    CP16((SB) + K1_BUHI + bd0, g_Wuh + bRow + ke0);                            \
    CP16((SB) + K1_BUHI + bd1, g_Wuh + bRow + ke0 + 8);                        \
    CP16((SB) + K1_BULO + bd0, g_Wul + bRow + ke0);                            \
    CP16((SB) + K1_BULO + bd1, g_Wul + bRow + ke0 + 8);                        \
    CP_COMMIT();                                                               \
} while (0)

    // ldmatrix lane geometry (R3)
    const int laneRow = ((lane >> 3) & 1) * 8 + (lane & 7);
    const int laneK   = (lane >> 4) * 16;
    const int R       = 32 * (wid & 3);
    const int bSec    = (wid >= 4) ? K1_BUHI : K1_BGHI;

    float acc[2][16][4];
#pragma unroll
    for (int f = 0; f < 2; f++)
#pragma unroll
        for (int n = 0; n < 16; n++)
#pragma unroll
            for (int q = 0; q < 4; q++) acc[f][n][q] = 0.f;

    // prologue: chunk 0
    float4 rA[4];
#pragma unroll
    for (int j = 0; j < 4; j++)
        rA[j] = *reinterpret_cast<const float4*>(pA[j]);
#pragma unroll
    for (int j = 0; j < 4; j++)
        split_store(sm + sts[j], sm + K1_ALO + sts[j], rA[j]);
    K1_ISSUE_B(smb, 0);

#pragma unroll 1
    for (int c = 0; c < NC1; c++) {
        CP_WAIT0();
        __syncthreads();
        const uint32_t sb = smb + (uint32_t)(c & 1) * STAGE1;
        char* nb = sm + (size_t)((c + 1) & 1) * STAGE1;
        if (c + 1 < NC1) {
            K1_ISSUE_B(smb + (uint32_t)((c + 1) & 1) * STAGE1, (c + 1) * 32);
            const int k0 = (c + 1) * 32;
#pragma unroll
            for (int j = 0; j < 4; j++)
                rA[j] = *reinterpret_cast<const float4*>(pA[j] + k0);
        }
        // MMA over current buffer (verbatim R3)
#pragma unroll
        for (int s = 0; s < 2; s++) {
            const uint32_t ab = sb + (uint32_t)((R + laneRow) * ROWB + laneK + 32 * s);
            uint32_t ah[2][4], al[2][4];
            ldsm4(ab,                      ah[0][0], ah[0][1], ah[0][2], ah[0][3]);
            ldsm4(ab + 16 * ROWB,          ah[1][0], ah[1][1], ah[1][2], ah[1][3]);
            ldsm4(ab + K1_ALO,             al[0][0], al[0][1], al[0][2], al[0][3]);
            ldsm4(ab + K1_ALO + 16 * ROWB, al[1][0], al[1][1], al[1][2], al[1][3]);
#pragma unroll
            for (int gp = 0; gp < 8; gp++) {
                const uint32_t bb = sb + (uint32_t)(bSec +
                    (16 * gp + laneRow) * ROWB + laneK + 32 * s);
                uint32_t bh[4], bl[4];
                ldsm4(bb,         bh[0], bh[1], bh[2], bh[3]);
                ldsm4(bb + 10240, bl[0], bl[1], bl[2], bl[3]);
#pragma unroll
                for (int f = 0; f < 2; f++)
#pragma unroll
                    for (int h = 0; h < 2; h++) {
                        float* cc = acc[f][2 * gp + h];
                        hmma(cc, ah[f], bh[h], bh[2 + h]);
                        hmma(cc, ah[f], bl[h], bl[2 + h]);
                        hmma(cc, al[f], bh[h], bh[2 + h]);
                    }
            }
        }
        if (c + 1 < NC1) {
#pragma unroll
            for (int j = 0; j < 4; j++)
                split_store(nb + sts[j], nb + K1_ALO + sts[j], rA[j]);
        }
    }

    // ---- epilogue (verbatim R3): up warps park in smem; gate warps combine --
    __syncthreads();
    float* upbuf = reinterpret_cast<float*>(sm);
    if (wid >= 4) {
        const int w = wid - 4;
#pragma unroll
        for (int f = 0; f < 2; f++)
#pragma unroll
            for (int n = 0; n < 16; n++) {
                int row = 16 * f + (lane >> 2);
                int col = 8 * n + (lane & 3) * 2;
                float* b0 = upbuf + w * 4224 + row * 132 + col;
                b0[0] = acc[f][n][0]; b0[1] = acc[f][n][1];
                float* b1 = b0 + 8 * 132;
                b1[0] = acc[f][n][2]; b1[1] = acc[f][n][3];
            }
    }
    __syncthreads();
    if (wid < 4) {
        const int w = wid;
#pragma unroll
        for (int f = 0; f < 2; f++)
#pragma unroll
            for (int n = 0; n < 16; n++) {
                int row = 16 * f + (lane >> 2);
                int col = 8 * n + (lane & 3) * 2;
                const float* b0 = upbuf + w * 4224 + row * 132 + col;
                const float* b1 = b0 + 8 * 132;
                float* o0 = g_h + (size_t)(m0 + 32 * w + row) * IDIM + n0 + col;
                float* o1 = o0 + (size_t)8 * IDIM;
                *reinterpret_cast<float2*>(o0) =
                    make_float2(silu(acc[f][n][0]) * b0[0],
                                silu(acc[f][n][1]) * b0[1]);
                *reinterpret_cast<float2*>(o1) =
                    make_float2(silu(acc[f][n][2]) * b1[0],
                                silu(acc[f][n][3]) * b1[1]);
            }
    }
}

// ---------------------------------------------------------------------------
// Kernel 2: down projection; A (g_h) register-staged+split, B (Wd) cp.async.
// R3 tiling: 8 warps 4m x 2n, warp 32x64.
// ---------------------------------------------------------------------------
__global__ __launch_bounds__(256)
void k2_down()
{
    extern __shared__ __align__(128) char sm[];
    const uint32_t smb = smem_u32(sm);
    const int tid  = threadIdx.x;
    const int wid  = tid >> 5;
    const int lane = tid & 31;
    const int m0 = blockIdx.x * 128;
    const int n0 = blockIdx.y * 128;

    const int rbase = tid >> 3;
    const int c4    = (tid & 7) * 4;
    const float* pA[4];
    int sts[4];
#pragma unroll
    for (int j = 0; j < 4; j++) {
        int row = rbase + 32 * j;
        pA[j] = g_h + (size_t)(m0 + row) * IDIM + c4;
        sts[j] = row * ROWB + (tid & 7) * 8;
    }

    const int brow  = tid >> 1;
    const int bch   = (tid & 1) * 2;
    const size_t bRow = (size_t)(n0 + brow) * IDIM;
    const uint32_t bd0 = (uint32_t)(brow * ROWB + bch * 16);
    const uint32_t bd1 = bd0 + 16;

#define K2_ISSUE_B(SB, K0) do {                                                \
    const int ke0 = (K0) + bch * 8;                                            \
    CP16((SB) + K2_BHI + bd0, g_Wdh + bRow + ke0);                             \
    CP16((SB) + K2_BHI + bd1, g_Wdh + bRow + ke0 + 8);                         \
    CP16((SB) + K2_BLO + bd0, g_Wdl + bRow + ke0);                             \
    CP16((SB) + K2_BLO + bd1, g_Wdl + bRow + ke0 + 8);                         \
    CP_COMMIT();                                                               \
} while (0)

    const int laneRow = ((lane >> 3) & 1) * 8 + (lane & 7);
    const int laneK   = (lane >> 4) * 16;
    const int R       = 32 * (wid & 3);
    const int cb      = 64 * (wid >> 2);

    float acc[2][8][4];
#pragma unroll
    for (int f = 0; f < 2; f++)
#pragma unroll
        for (int n = 0; n < 8; n++)
#pragma unroll
            for (int q = 0; q < 4; q++) acc[f][n][q] = 0.f;

    float4 rA[4];
#pragma unroll
    for (int j = 0; j < 4; j++)
        rA[j] = *reinterpret_cast<const float4*>(pA[j]);
#pragma unroll
    for (int j = 0; j < 4; j++)
        split_store(sm + sts[j], sm + K2_ALO + sts[j], rA[j]);
    K2_ISSUE_B(smb, 0);

#pragma unroll 1
    for (int c = 0; c < NC2; c++) {
        CP_WAIT0();
        __syncthreads();
        const uint32_t sb = smb + (uint32_t)(c & 1) * STAGE2;
        char* nb = sm + (size_t)((c + 1) & 1) * STAGE2;
        if (c + 1 < NC2) {
            K2_ISSUE_B(smb + (uint32_t)((c + 1) & 1) * STAGE2, (c + 1) * 32);
            const int k0 = (c + 1) * 32;
#pragma unroll
            for (int j = 0; j < 4; j++)
                rA[j] = *reinterpret_cast<const float4*>(pA[j] + k0);
        }
#pragma unroll
        for (int s = 0; s < 2; s++) {
            const uint32_t ab = sb + (uint32_t)((R + laneRow) * ROWB + laneK + 32 * s);
            uint32_t ah[2][4], al[2][4];
            ldsm4(ab,                      ah[0][0], ah[0][1], ah[0][2], ah[0][3]);
            ldsm4(ab + 16 * ROWB,          ah[1][0], ah[1][1], ah[1][2], ah[1][3]);
            ldsm4(ab + K2_ALO,             al[0][0], al[0][1], al[0][2], al[0][3]);
            ldsm4(ab + K2_ALO + 16 * ROWB, al[1][0], al[1][1], al[1][2], al[1][3]);
#pragma unroll
            for (int gp = 0; gp < 4; gp++) {
                const uint32_t bb = sb + (uint32_t)(K2_BHI +
                    (cb + 16 * gp + laneRow) * ROWB + laneK + 32 * s);
                uint32_t bh[4], bl[4];
                ldsm4(bb,         bh[0], bh[1], bh[2], bh[3]);
                ldsm4(bb + 10240, bl[0], bl[1], bl[2], bl[3]);
#pragma unroll
                for (int f = 0; f < 2; f++)
#pragma unroll
                    for (int h = 0; h < 2; h++) {
                        float* cc = acc[f][2 * gp + h];
                        hmma(cc, ah[f], bh[h], bh[2 + h]);
                        hmma(cc, ah[f], bl[h], bl[2 + h]);
                        hmma(cc, al[f], bh[h], bh[2 + h]);
                    }
            }
        }
        if (c + 1 < NC2) {
#pragma unroll
            for (int j = 0; j < 4; j++)
                split_store(nb + sts[j], nb + K2_ALO + sts[j], rA[j]);
        }
    }

#pragma unroll
    for (int f = 0; f < 2; f++)
#pragma unroll
        for (int n = 0; n < 8; n++) {
            int row = R + 16 * f + (lane >> 2);
            int col = n0 + cb + 8 * n + (lane & 3) * 2;
            float* o0 = g_down + (size_t)(m0 + row) * HDIM + col;
            float* o1 = o0 + (size_t)8 * HDIM;
            *reinterpret_cast<float2*>(o0) = make_float2(acc[f][n][0], acc[f][n][1]);
            *reinterpret_cast<float2*>(o1) = make_float2(acc[f][n][2], acc[f][n][3]);
        }
}

// ---------------------------------------------------------------------------
// Kernel 3: scatter
// ---------------------------------------------------------------------------
__global__ __launch_bounds__(256)
void scatter_kernel(const int* __restrict__ scatter_indices,
                    float* __restrict__ out)
{
    const int t = blockIdx.x;
    const int c = scatter_indices[t];
    const float4* src = reinterpret_cast<const float4*>(g_down + (size_t)c * HDIM);
    float4*       dst = reinterpret_cast<float4*>(out + (size_t)t * HDIM);
#pragma unroll
    for (int j = threadIdx.x; j < HDIM / 4; j += 256)
        dst[j] = src[j];
}

// ---------------------------------------------------------------------------
extern "C" void kernel_launch(void* const* d_in, const int* in_sizes, int n_in,
                              void* d_out, int out_size)
{
    const float* x  = (const float*)d_in[0];
    const float* Wg = (const float*)d_in[1];
    const float* Wu = (const float*)d_in[2];
    const float* Wd = (const float*)d_in[3];
    const int*   fg = (const int*)d_in[4];
    const int*   sc = (const int*)d_in[5];
    float*       out = (float*)d_out;

    cudaFuncSetAttribute(k1_gateup, cudaFuncAttributeMaxDynamicSharedMemorySize, SMEM1);
    cudaFuncSetAttribute(k2_down,   cudaFuncAttributeMaxDynamicSharedMemorySize, SMEM2);

    __nv_bfloat16 *wgh, *wgl, *wuh, *wul, *wdh, *wdl;
    cudaGetSymbolAddress((void**)&wgh, g_Wgh);
    cudaGetSymbolAddress((void**)&wgl, g_Wgl);
    cudaGetSymbolAddress((void**)&wuh, g_Wuh);
    cudaGetSymbolAddress((void**)&wul, g_Wul);
    cudaGetSymbolAddress((void**)&wdh, g_Wdh);
    cudaGetSymbolAddress((void**)&wdl, g_Wdl);

    const int n4 = (IDIM * HDIM) / 4;
    conv_w<<<4096, 256>>>((const float4*)Wg, wgh, wgl, n4);
    conv_w<<<4096, 256>>>((const float4*)Wu, wuh, wul, n4);
    conv_w<<<4096, 256>>>((const float4*)Wd, wdh, wdl, n4);

    dim3 g1(CDIM / 128, IDIM / 128);   // m fastest
    k1_gateup<<<g1, 256, SMEM1>>>(x, fg);

    dim3 g2(CDIM / 128, HDIM / 128);   // m fastest
    k2_down<<<g2, 256, SMEM2>>>();

    scatter_kernel<<<NTOK, 256>>>(sc, out);
}